// round 8
// baseline (speedup 1.0000x reference)
#include <cuda_runtime.h>
#include <cstdint>

// KNN: B=4, N=8192, D=16, K=16. Output float32 [B, N, K] neighbor indices,
// ascending distance, ties -> lower index (matches jax.lax.top_k).
//
// R7 optimization: 2 rows/thread (amortize candidate loads), LDS.128 reads,
// TJ=512 tiles, 256 blocks x 64 threads for full-chip coverage.
// Per-row arithmetic identical to the passing R6 kernel (rel_err 1.79e-4).

#define BATCH 4
#define NPTS  8192
#define DIM   16
#define KSEL  16
#define TJ    512
#define NTILES (NPTS / TJ)
#define THREADS 64
#define ROWS_PB 128            // 2 rows per thread
#define X_ELEMS (BATCH * NPTS * DIM)

__device__ __forceinline__ void unpack16(const float4* pv, float* p) {
    float4 a = pv[0], b = pv[1], c = pv[2], d = pv[3];
    p[0]=a.x; p[1]=a.y; p[2]=a.z; p[3]=a.w;
    p[4]=b.x; p[5]=b.y; p[6]=b.z; p[7]=b.w;
    p[8]=c.x; p[9]=c.y; p[10]=c.z; p[11]=c.w;
    p[12]=d.x; p[13]=d.y; p[14]=d.z; p[15]=d.w;
}

__device__ __forceinline__ float dist16(const float* q, const float* p,
                                        float ni, float nj) {
    float dot = __fmul_rn(q[0], p[0]);
#pragma unroll
    for (int k = 1; k < DIM; ++k)
        dot = __fmaf_rn(q[k], p[k], dot);
    float t1 = __fadd_rn(ni, __fmul_rn(-2.0f, dot));
    return __fadd_rn(t1, nj);
}

// strict-< insertion keeps jax.lax.top_k tie order (earlier j wins)
__device__ __forceinline__ void insert16(float* d, int* id, float dist, int j) {
    if (dist < d[KSEL - 1]) {
        d[KSEL - 1]  = dist;
        id[KSEL - 1] = j;
#pragma unroll
        for (int t = KSEL - 1; t > 0; --t) {
            if (d[t] < d[t - 1]) {
                float tf = d[t - 1];  d[t - 1]  = d[t];  d[t]  = tf;
                int   ti = id[t - 1]; id[t - 1] = id[t]; id[t] = ti;
            }
        }
    }
}

__global__ void __launch_bounds__(THREADS)
knn_kernel(const float* __restrict__ x, float* __restrict__ out) {
    __shared__ __align__(16) float s_pts[TJ * DIM];   // 32 KB
    __shared__ __align__(16) float s_nrm[TJ];         //  2 KB

    const int tid   = threadIdx.x;
    const int grow0 = blockIdx.x * ROWS_PB + tid;     // rows grow0, grow0+64
    const int batch = grow0 >> 13;
    const int row0  = grow0 & (NPTS - 1);
    const int row1  = row0 + THREADS;

    const float* xb = x + (size_t)batch * NPTS * DIM;

    // two queries into registers + their norms (same order as R6)
    float q0[DIM], q1[DIM];
    unpack16((const float4*)(xb + (size_t)row0 * DIM), q0);
    unpack16((const float4*)(xb + (size_t)row1 * DIM), q1);
    float ni0 = __fmul_rn(q0[0], q0[0]);
    float ni1 = __fmul_rn(q1[0], q1[0]);
#pragma unroll
    for (int k = 1; k < DIM; ++k) {
        ni0 = __fadd_rn(ni0, __fmul_rn(q0[k], q0[k]));
        ni1 = __fadd_rn(ni1, __fmul_rn(q1[k], q1[k]));
    }

    float d0[KSEL], d1[KSEL];
    int   id0[KSEL], id1[KSEL];
#pragma unroll
    for (int t = 0; t < KSEL; ++t) {
        d0[t] = __int_as_float(0x7F800000); id0[t] = 0;
        d1[t] = __int_as_float(0x7F800000); id1[t] = 0;
    }

    for (int tile = 0; tile < NTILES; ++tile) {
        const int jbase = tile * TJ;

        // cooperative coalesced tile load
        {
            const float4* src = (const float4*)(xb + (size_t)jbase * DIM);
            float4* dst = (float4*)s_pts;
#pragma unroll
            for (int v = 0; v < TJ * DIM / 4 / THREADS; ++v)
                dst[tid + v * THREADS] = src[tid + v * THREADS];
        }
        __syncthreads();

        // tile norms (8 points per thread), same arithmetic as queries
#pragma unroll
        for (int v = 0; v < TJ / THREADS; ++v) {
            int jl = tid + v * THREADS;
            float pt[DIM];
            unpack16((const float4*)(s_pts + jl * DIM), pt);
            float s = __fmul_rn(pt[0], pt[0]);
#pragma unroll
            for (int k = 1; k < DIM; ++k)
                s = __fadd_rn(s, __fmul_rn(pt[k], pt[k]));
            s_nrm[jl] = s;
        }
        __syncthreads();

        // scan: all threads walk the same jl (broadcast LDS.128), 2 candidates/iter
#pragma unroll 2
        for (int jl = 0; jl < TJ; ++jl) {
            float p[DIM];
            unpack16((const float4*)(s_pts + jl * DIM), p);
            const float nj = s_nrm[jl];
            float da = dist16(q0, p, ni0, nj);
            float db = dist16(q1, p, ni1, nj);
            insert16(d0, id0, da, jbase + jl);
            insert16(d1, id1, db, jbase + jl);
        }
        __syncthreads();
    }

    float* op0 = out + (size_t)(batch * NPTS + row0) * KSEL;
    float* op1 = out + (size_t)(batch * NPTS + row1) * KSEL;
#pragma unroll
    for (int t = 0; t < KSEL; ++t) {
        op0[t] = (float)id0[t];
        op1[t] = (float)id1[t];
    }
}

extern "C" void kernel_launch(void* const* d_in, const int* in_sizes, int n_in,
                              void* d_out, int out_size) {
    const float* x = nullptr;
    for (int i = 0; i < n_in; ++i)
        if (in_sizes[i] == X_ELEMS) { x = (const float*)d_in[i]; break; }
    if (!x)
        for (int i = 0; i < n_in; ++i)
            if (in_sizes[i] == X_ELEMS * 4) { x = (const float*)d_in[i]; break; }
    if (!x) {
        int best = 0;
        for (int i = 1; i < n_in; ++i)
            if (in_sizes[i] > in_sizes[best]) best = i;
        x = (const float*)d_in[best];
    }
    knn_kernel<<<BATCH * NPTS / ROWS_PB, THREADS>>>(x, (float*)d_out);
}

// round 9
// speedup vs baseline: 1.1795x; 1.1795x over previous
#include <cuda_runtime.h>
#include <cstdint>

// KNN: B=4, N=8192, D=16, K=16. Output float32 [B, N, K] neighbor indices,
// ascending distance, ties -> lower index (matches jax.lax.top_k).
//
// R9: one row/thread (regs back to ~90, R8's dual-list 162-reg collapse undone),
// 512 x 64 launch for full-chip coverage + latency hiding, vector LDS.128
// candidate reads, unroll-2 candidate ILP. Per-row arithmetic bit-identical
// to the passing R6/R7 kernels (rel_err 1.790007e-4).

#define BATCH 4
#define NPTS  8192
#define DIM   16
#define KSEL  16
#define TJ    512
#define NTILES (NPTS / TJ)
#define THREADS 64
#define X_ELEMS (BATCH * NPTS * DIM)

__device__ __forceinline__ void unpack16(const float4* pv, float* p) {
    float4 a = pv[0], b = pv[1], c = pv[2], d = pv[3];
    p[0]=a.x; p[1]=a.y; p[2]=a.z; p[3]=a.w;
    p[4]=b.x; p[5]=b.y; p[6]=b.z; p[7]=b.w;
    p[8]=c.x; p[9]=c.y; p[10]=c.z; p[11]=c.w;
    p[12]=d.x; p[13]=d.y; p[14]=d.z; p[15]=d.w;
}

__global__ void __launch_bounds__(THREADS)
knn_kernel(const float* __restrict__ x, float* __restrict__ out) {
    __shared__ __align__(16) float s_pts[TJ * DIM];   // 32 KB
    __shared__ __align__(16) float s_nrm[TJ];         //  2 KB

    const int tid   = threadIdx.x;
    const int grow  = blockIdx.x * THREADS + tid;     // global row 0..32767
    const int batch = grow >> 13;
    const int row   = grow & (NPTS - 1);

    const float* xb = x + (size_t)batch * NPTS * DIM;

    // query into registers + own norm (same order as passing kernels)
    float q[DIM];
    unpack16((const float4*)(xb + (size_t)row * DIM), q);
    float ni = __fmul_rn(q[0], q[0]);
#pragma unroll
    for (int k = 1; k < DIM; ++k)
        ni = __fadd_rn(ni, __fmul_rn(q[k], q[k]));

    // selection list: sorted ascending by (distance, index)
    float d[KSEL];
    int   id[KSEL];
#pragma unroll
    for (int t = 0; t < KSEL; ++t) { d[t] = __int_as_float(0x7F800000); id[t] = 0; }

    for (int tile = 0; tile < NTILES; ++tile) {
        const int jbase = tile * TJ;

        // cooperative coalesced tile load
        {
            const float4* src = (const float4*)(xb + (size_t)jbase * DIM);
            float4* dst = (float4*)s_pts;
#pragma unroll
            for (int v = 0; v < TJ * DIM / 4 / THREADS; ++v)
                dst[tid + v * THREADS] = src[tid + v * THREADS];
        }
        __syncthreads();

        // tile norms (8 points per thread), identical arithmetic to queries
#pragma unroll
        for (int v = 0; v < TJ / THREADS; ++v) {
            int jl = tid + v * THREADS;
            float pt[DIM];
            unpack16((const float4*)(s_pts + jl * DIM), pt);
            float s = __fmul_rn(pt[0], pt[0]);
#pragma unroll
            for (int k = 1; k < DIM; ++k)
                s = __fadd_rn(s, __fmul_rn(pt[k], pt[k]));
            s_nrm[jl] = s;
        }
        __syncthreads();

        // scan: all threads walk the same jl (broadcast LDS.128);
        // unroll 2 -> two independent fma chains in flight per thread
#pragma unroll 2
        for (int jl = 0; jl < TJ; ++jl) {
            float p[DIM];
            unpack16((const float4*)(s_pts + jl * DIM), p);
            float dot = __fmul_rn(q[0], p[0]);
#pragma unroll
            for (int k = 1; k < DIM; ++k)
                dot = __fmaf_rn(q[k], p[k], dot);
            float t1   = __fadd_rn(ni, __fmul_rn(-2.0f, dot));
            float dist = __fadd_rn(t1, s_nrm[jl]);

            if (dist < d[KSEL - 1]) {              // strict: ties keep earlier j
                d[KSEL - 1]  = dist;
                id[KSEL - 1] = jbase + jl;
#pragma unroll
                for (int t = KSEL - 1; t > 0; --t) {
                    if (d[t] < d[t - 1]) {
                        float tf = d[t - 1];  d[t - 1]  = d[t];  d[t]  = tf;
                        int   ti = id[t - 1]; id[t - 1] = id[t]; id[t] = ti;
                    }
                }
            }
        }
        __syncthreads();
    }

    float* op = out + (size_t)grow * KSEL;
#pragma unroll
    for (int t = 0; t < KSEL; ++t)
        op[t] = (float)id[t];
}

extern "C" void kernel_launch(void* const* d_in, const int* in_sizes, int n_in,
                              void* d_out, int out_size) {
    const float* x = nullptr;
    for (int i = 0; i < n_in; ++i)
        if (in_sizes[i] == X_ELEMS) { x = (const float*)d_in[i]; break; }
    if (!x)
        for (int i = 0; i < n_in; ++i)
            if (in_sizes[i] == X_ELEMS * 4) { x = (const float*)d_in[i]; break; }
    if (!x) {
        int best = 0;
        for (int i = 1; i < n_in; ++i)
            if (in_sizes[i] > in_sizes[best]) best = i;
        x = (const float*)d_in[best];
    }
    knn_kernel<<<BATCH * NPTS / THREADS, THREADS>>>(x, (float*)d_out);
}

// round 10
// speedup vs baseline: 1.4338x; 1.2156x over previous
#include <cuda_runtime.h>
#include <cstdint>

// KNN: B=4, N=8192, D=16, K=16. Output float32 [B, N, K] neighbor indices,
// ascending distance, ties -> lower index (matches jax.lax.top_k).
//
// R10: register-lean scan. Candidates consumed directly from float4 quads
// (no unpack arrays), hard 128-reg cap, TJ=256, unroll-4 fma-chain ILP.
// Per-row arithmetic bit-identical to the passing kernels (rel_err 1.79e-4).

#define BATCH 4
#define NPTS  8192
#define DIM   16
#define KSEL  16
#define TJ    256
#define NTILES (NPTS / TJ)
#define THREADS 64
#define X_ELEMS (BATCH * NPTS * DIM)

__global__ void __launch_bounds__(THREADS, 8)
knn_kernel(const float* __restrict__ x, float* __restrict__ out) {
    __shared__ __align__(16) float s_pts[TJ * DIM];   // 16 KB
    __shared__ __align__(16) float s_nrm[TJ];         //  1 KB

    const int tid   = threadIdx.x;
    const int grow  = blockIdx.x * THREADS + tid;     // global row 0..32767
    const int batch = grow >> 13;
    const int row   = grow & (NPTS - 1);

    const float* xb = x + (size_t)batch * NPTS * DIM;

    // query into registers + own norm (same order as passing kernels)
    float q[DIM];
    {
        const float4* qv = (const float4*)(xb + (size_t)row * DIM);
        float4 a = qv[0], b = qv[1], c = qv[2], e = qv[3];
        q[0]=a.x; q[1]=a.y; q[2]=a.z; q[3]=a.w;
        q[4]=b.x; q[5]=b.y; q[6]=b.z; q[7]=b.w;
        q[8]=c.x; q[9]=c.y; q[10]=c.z; q[11]=c.w;
        q[12]=e.x; q[13]=e.y; q[14]=e.z; q[15]=e.w;
    }
    float ni = __fmul_rn(q[0], q[0]);
#pragma unroll
    for (int k = 1; k < DIM; ++k)
        ni = __fadd_rn(ni, __fmul_rn(q[k], q[k]));

    // selection list: sorted ascending by (distance, index)
    float d[KSEL];
    int   id[KSEL];
#pragma unroll
    for (int t = 0; t < KSEL; ++t) { d[t] = __int_as_float(0x7F800000); id[t] = 0; }

    for (int tile = 0; tile < NTILES; ++tile) {
        const int jbase = tile * TJ;

        // cooperative coalesced tile load
        {
            const float4* src = (const float4*)(xb + (size_t)jbase * DIM);
            float4* dst = (float4*)s_pts;
#pragma unroll
            for (int v = 0; v < TJ * DIM / 4 / THREADS; ++v)
                dst[tid + v * THREADS] = src[tid + v * THREADS];
        }
        __syncthreads();

        // tile norms (TJ/THREADS points per thread), identical arithmetic
#pragma unroll
        for (int v = 0; v < TJ / THREADS; ++v) {
            int jl = tid + v * THREADS;
            const float4* pv = (const float4*)(s_pts + jl * DIM);
            float4 a = pv[0], b = pv[1], c = pv[2], e = pv[3];
            float s = __fmul_rn(a.x, a.x);
            s = __fadd_rn(s, __fmul_rn(a.y, a.y));
            s = __fadd_rn(s, __fmul_rn(a.z, a.z));
            s = __fadd_rn(s, __fmul_rn(a.w, a.w));
            s = __fadd_rn(s, __fmul_rn(b.x, b.x));
            s = __fadd_rn(s, __fmul_rn(b.y, b.y));
            s = __fadd_rn(s, __fmul_rn(b.z, b.z));
            s = __fadd_rn(s, __fmul_rn(b.w, b.w));
            s = __fadd_rn(s, __fmul_rn(c.x, c.x));
            s = __fadd_rn(s, __fmul_rn(c.y, c.y));
            s = __fadd_rn(s, __fmul_rn(c.z, c.z));
            s = __fadd_rn(s, __fmul_rn(c.w, c.w));
            s = __fadd_rn(s, __fmul_rn(e.x, e.x));
            s = __fadd_rn(s, __fmul_rn(e.y, e.y));
            s = __fadd_rn(s, __fmul_rn(e.z, e.z));
            s = __fadd_rn(s, __fmul_rn(e.w, e.w));
            s_nrm[jl] = s;
        }
        __syncthreads();

        // scan: all threads walk the same jl (broadcast LDS.128);
        // float4 quads consumed directly -> minimal live registers
#pragma unroll 4
        for (int jl = 0; jl < TJ; ++jl) {
            const float4* pv = (const float4*)(s_pts + jl * DIM);
            float4 a = pv[0], b = pv[1], c = pv[2], e = pv[3];
            float dot = __fmul_rn(q[0], a.x);
            dot = __fmaf_rn(q[1],  a.y, dot);
            dot = __fmaf_rn(q[2],  a.z, dot);
            dot = __fmaf_rn(q[3],  a.w, dot);
            dot = __fmaf_rn(q[4],  b.x, dot);
            dot = __fmaf_rn(q[5],  b.y, dot);
            dot = __fmaf_rn(q[6],  b.z, dot);
            dot = __fmaf_rn(q[7],  b.w, dot);
            dot = __fmaf_rn(q[8],  c.x, dot);
            dot = __fmaf_rn(q[9],  c.y, dot);
            dot = __fmaf_rn(q[10], c.z, dot);
            dot = __fmaf_rn(q[11], c.w, dot);
            dot = __fmaf_rn(q[12], e.x, dot);
            dot = __fmaf_rn(q[13], e.y, dot);
            dot = __fmaf_rn(q[14], e.z, dot);
            dot = __fmaf_rn(q[15], e.w, dot);
            float t1   = __fadd_rn(ni, __fmul_rn(-2.0f, dot));
            float dist = __fadd_rn(t1, s_nrm[jl]);

            if (dist < d[KSEL - 1]) {              // strict: ties keep earlier j
                d[KSEL - 1]  = dist;
                id[KSEL - 1] = jbase + jl;
#pragma unroll
                for (int t = KSEL - 1; t > 0; --t) {
                    if (d[t] < d[t - 1]) {
                        float tf = d[t - 1];  d[t - 1]  = d[t];  d[t]  = tf;
                        int   ti = id[t - 1]; id[t - 1] = id[t]; id[t] = ti;
                    }
                }
            }
        }
        __syncthreads();
    }

    float* op = out + (size_t)grow * KSEL;
#pragma unroll
    for (int t = 0; t < KSEL; ++t)
        op[t] = (float)id[t];
}

extern "C" void kernel_launch(void* const* d_in, const int* in_sizes, int n_in,
                              void* d_out, int out_size) {
    const float* x = nullptr;
    for (int i = 0; i < n_in; ++i)
        if (in_sizes[i] == X_ELEMS) { x = (const float*)d_in[i]; break; }
    if (!x)
        for (int i = 0; i < n_in; ++i)
            if (in_sizes[i] == X_ELEMS * 4) { x = (const float*)d_in[i]; break; }
    if (!x) {
        int best = 0;
        for (int i = 1; i < n_in; ++i)
            if (in_sizes[i] > in_sizes[best]) best = i;
        x = (const float*)d_in[best];
    }
    knn_kernel<<<BATCH * NPTS / THREADS, THREADS>>>(x, (float*)d_out);
}

// round 11
// speedup vs baseline: 1.5169x; 1.0579x over previous
#include <cuda_runtime.h>
#include <cstdint>

// KNN: B=4, N=8192, D=16, K=16. Output float32 [B, N, K] neighbor indices.
// R11: split-j decomposition. 1024 scan blocks (2x warp residency vs R10),
// each covers half the candidate range for 64 rows -> partial sorted top-16
// into device scratch; merge kernel combines. Distance arithmetic bit-identical
// to R10 (rel_err 1.790007e-4).

#define BATCH 4
#define NPTS  8192
#define DIM   16
#define KSEL  16
#define HALF  (NPTS / 2)      // 4096 candidates per scan block
#define TJ    256
#define NTILES_H (HALF / TJ)  // 16
#define THREADS 64
#define NROWS (BATCH * NPTS)  // 32768
#define X_ELEMS (NROWS * DIM)

__device__ __align__(16) float g_norms[NROWS];
__device__ __align__(16) float g_pd[NROWS * 2 * KSEL];   // partial dists
__device__ __align__(16) int   g_pi[NROWS * 2 * KSEL];   // partial indices

__global__ void knn_norms(const float* __restrict__ x) {
    int p = blockIdx.x * blockDim.x + threadIdx.x;   // 0..32767
    const float4* v = (const float4*)(x + (size_t)p * DIM);
    float4 a = v[0], b = v[1], c = v[2], e = v[3];
    float s = __fmul_rn(a.x, a.x);
    s = __fadd_rn(s, __fmul_rn(a.y, a.y));
    s = __fadd_rn(s, __fmul_rn(a.z, a.z));
    s = __fadd_rn(s, __fmul_rn(a.w, a.w));
    s = __fadd_rn(s, __fmul_rn(b.x, b.x));
    s = __fadd_rn(s, __fmul_rn(b.y, b.y));
    s = __fadd_rn(s, __fmul_rn(b.z, b.z));
    s = __fadd_rn(s, __fmul_rn(b.w, b.w));
    s = __fadd_rn(s, __fmul_rn(c.x, c.x));
    s = __fadd_rn(s, __fmul_rn(c.y, c.y));
    s = __fadd_rn(s, __fmul_rn(c.z, c.z));
    s = __fadd_rn(s, __fmul_rn(c.w, c.w));
    s = __fadd_rn(s, __fmul_rn(e.x, e.x));
    s = __fadd_rn(s, __fmul_rn(e.y, e.y));
    s = __fadd_rn(s, __fmul_rn(e.z, e.z));
    s = __fadd_rn(s, __fmul_rn(e.w, e.w));
    g_norms[p] = s;
}

__global__ void __launch_bounds__(THREADS, 8)
knn_scan(const float* __restrict__ x) {
    __shared__ __align__(16) float s_pts[TJ * DIM];   // 16 KB
    __shared__ __align__(16) float s_nrm[TJ];         //  1 KB

    const int bid   = blockIdx.x;
    const int half  = bid & 1;                 // candidate half 0/1
    const int rb    = bid >> 1;                // row-block 0..511
    const int tid   = threadIdx.x;
    const int grow  = rb * THREADS + tid;      // global row 0..32767
    const int batch = grow >> 13;
    const int row   = grow & (NPTS - 1);

    const float* xb = x + (size_t)batch * NPTS * DIM;
    const float* nb = g_norms + batch * NPTS;

    // query into registers + own norm (precomputed, bit-identical)
    float q[DIM];
    {
        const float4* qv = (const float4*)(xb + (size_t)row * DIM);
        float4 a = qv[0], b = qv[1], c = qv[2], e = qv[3];
        q[0]=a.x; q[1]=a.y; q[2]=a.z; q[3]=a.w;
        q[4]=b.x; q[5]=b.y; q[6]=b.z; q[7]=b.w;
        q[8]=c.x; q[9]=c.y; q[10]=c.z; q[11]=c.w;
        q[12]=e.x; q[13]=e.y; q[14]=e.z; q[15]=e.w;
    }
    const float ni = nb[row];

    float d[KSEL];
    int   id[KSEL];
#pragma unroll
    for (int t = 0; t < KSEL; ++t) { d[t] = __int_as_float(0x7F800000); id[t] = 0; }

    const int jstart = half * HALF;

    for (int tile = 0; tile < NTILES_H; ++tile) {
        const int jbase = jstart + tile * TJ;

        // cooperative tile load: points + norms
        {
            const float4* src = (const float4*)(xb + (size_t)jbase * DIM);
            float4* dst = (float4*)s_pts;
#pragma unroll
            for (int v = 0; v < TJ * DIM / 4 / THREADS; ++v)
                dst[tid + v * THREADS] = src[tid + v * THREADS];
            ((float4*)s_nrm)[tid] = ((const float4*)(nb + jbase))[tid];
        }
        __syncthreads();

        // scan: broadcast LDS.128, quads consumed directly
#pragma unroll 4
        for (int jl = 0; jl < TJ; ++jl) {
            const float4* pv = (const float4*)(s_pts + jl * DIM);
            float4 a = pv[0], b = pv[1], c = pv[2], e = pv[3];
            float dot = __fmul_rn(q[0], a.x);
            dot = __fmaf_rn(q[1],  a.y, dot);
            dot = __fmaf_rn(q[2],  a.z, dot);
            dot = __fmaf_rn(q[3],  a.w, dot);
            dot = __fmaf_rn(q[4],  b.x, dot);
            dot = __fmaf_rn(q[5],  b.y, dot);
            dot = __fmaf_rn(q[6],  b.z, dot);
            dot = __fmaf_rn(q[7],  b.w, dot);
            dot = __fmaf_rn(q[8],  c.x, dot);
            dot = __fmaf_rn(q[9],  c.y, dot);
            dot = __fmaf_rn(q[10], c.z, dot);
            dot = __fmaf_rn(q[11], c.w, dot);
            dot = __fmaf_rn(q[12], e.x, dot);
            dot = __fmaf_rn(q[13], e.y, dot);
            dot = __fmaf_rn(q[14], e.z, dot);
            dot = __fmaf_rn(q[15], e.w, dot);
            float t1   = __fadd_rn(ni, __fmul_rn(-2.0f, dot));
            float dist = __fadd_rn(t1, s_nrm[jl]);

            if (dist < d[KSEL - 1]) {              // strict: ties keep earlier j
                d[KSEL - 1]  = dist;
                id[KSEL - 1] = jbase + jl;
#pragma unroll
                for (int t = KSEL - 1; t > 0; --t) {
                    if (d[t] < d[t - 1]) {
                        float tf = d[t - 1];  d[t - 1]  = d[t];  d[t]  = tf;
                        int   ti = id[t - 1]; id[t - 1] = id[t]; id[t] = ti;
                    }
                }
            }
        }
        __syncthreads();
    }

    // write sorted partial list
    float* pd = g_pd + ((size_t)grow * 2 + half) * KSEL;
    int*   pi = g_pi + ((size_t)grow * 2 + half) * KSEL;
#pragma unroll
    for (int t = 0; t < KSEL; ++t) { pd[t] = d[t]; pi[t] = id[t]; }
}

__global__ void knn_merge(float* __restrict__ out) {
    const int grow = blockIdx.x * blockDim.x + threadIdx.x;  // 0..32767
    const float* d0 = g_pd + (size_t)grow * 2 * KSEL;
    const float* d1 = d0 + KSEL;
    const int*   i0 = g_pi + (size_t)grow * 2 * KSEL;
    const int*   i1 = i0 + KSEL;
    float* op = out + (size_t)grow * KSEL;

    int a = 0, b = 0;
    // all half-0 indices < half-1 indices, so ties (d0==d1) must take list 0
    // -> exact (dist, idx) lexicographic merge.
#pragma unroll
    for (int t = 0; t < KSEL; ++t) {
        float da = __ldg(d0 + a);
        float db = __ldg(d1 + b);
        bool take0 = (da <= db);
        int idx = take0 ? __ldg(i0 + a) : __ldg(i1 + b);
        a += take0 ? 1 : 0;
        b += take0 ? 0 : 1;
        op[t] = (float)idx;
    }
}

extern "C" void kernel_launch(void* const* d_in, const int* in_sizes, int n_in,
                              void* d_out, int out_size) {
    const float* x = nullptr;
    for (int i = 0; i < n_in; ++i)
        if (in_sizes[i] == X_ELEMS) { x = (const float*)d_in[i]; break; }
    if (!x)
        for (int i = 0; i < n_in; ++i)
            if (in_sizes[i] == X_ELEMS * 4) { x = (const float*)d_in[i]; break; }
    if (!x) {
        int best = 0;
        for (int i = 1; i < n_in; ++i)
            if (in_sizes[i] > in_sizes[best]) best = i;
        x = (const float*)d_in[best];
    }
    knn_norms<<<NROWS / 256, 256>>>(x);
    knn_scan<<<(NROWS / THREADS) * 2, THREADS>>>(x);
    knn_merge<<<NROWS / 256, 256>>>((float*)d_out);
}